// round 10
// baseline (speedup 1.0000x reference)
#include <cuda_runtime.h>
#include <cuda_bf16.h>

// SoftPool2d: x (16, 96, 256, 256) f32, 2x2 window, stride 2, no pad.
// out (16, 96, 128, 128) f32.
//
// Pure streaming (no reuse): read 402.7MB + write 100.7MB -> HBM-bound.
// R9 (resubmit; R4-R8 were infra failures, kernel never ran): 8 outputs per
// thread. Each thread loads 4x float4 from each of the 2 input rows
// (8 front-batched LDG.128 -> MLP_p1=8), computes 8 windows, stores two
// float4. Streaming cache hints (ldcs/stcs): every byte touched exactly once.

#define H 256
#define W 256
#define HO 128
#define WO 128

// octets of output pixels: (B*C) * HO * (WO/8) = 1536 * 128 * 16
#define NOCT (16 * 96 * 128 * 16)

__device__ __forceinline__ float softpool4(float t0, float t1, float t2, float t3) {
    float m = fmaxf(fmaxf(t0, t1), fmaxf(t2, t3));
    float e0 = __expf(t0 - m);
    float e1 = __expf(t1 - m);
    float e2 = __expf(t2 - m);
    float e3 = __expf(t3 - m);
    float num = fmaf(t0, e0, fmaf(t1, e1, fmaf(t2, e2, t3 * e3)));
    float den = e0 + e1 + e2 + e3;
    return num * __fdividef(1.0f, den);
}

__global__ __launch_bounds__(256) void SoftPool2d_850403524762_kernel(
    const float* __restrict__ x, float* __restrict__ out) {
    int idx = blockIdx.x * blockDim.x + threadIdx.x;
    if (idx >= NOCT) return;

    int wg = idx & 15;          // which 16-col group along W (16 groups)
    int ho = (idx >> 4) & 127;  // output row
    int bc = idx >> 11;         // fused batch*channel plane

    // input rows 2*ho and 2*ho+1 of plane bc; 16 input cols -> 4 float4 per row
    const float4* r0 = (const float4*)(x + (size_t)bc * (H * W) + (size_t)(2 * ho) * W) + 4 * wg;
    const float4* r1 = r0 + (W / 4);

    // 8 independent streaming loads, front-batched
    float4 a0 = __ldcs(r0 + 0);
    float4 a1 = __ldcs(r0 + 1);
    float4 a2 = __ldcs(r0 + 2);
    float4 a3 = __ldcs(r0 + 3);
    float4 b0 = __ldcs(r1 + 0);
    float4 b1 = __ldcs(r1 + 1);
    float4 b2 = __ldcs(r1 + 2);
    float4 b3 = __ldcs(r1 + 3);

    float4 o0, o1;
    o0.x = softpool4(a0.x, a0.y, b0.x, b0.y);
    o0.y = softpool4(a0.z, a0.w, b0.z, b0.w);
    o0.z = softpool4(a1.x, a1.y, b1.x, b1.y);
    o0.w = softpool4(a1.z, a1.w, b1.z, b1.w);
    o1.x = softpool4(a2.x, a2.y, b2.x, b2.y);
    o1.y = softpool4(a2.z, a2.w, b2.z, b2.w);
    o1.z = softpool4(a3.x, a3.y, b3.x, b3.y);
    o1.w = softpool4(a3.z, a3.w, b3.z, b3.w);

    float4* orow = (float4*)(out + (size_t)bc * (HO * WO) + (size_t)ho * WO) + 2 * wg;
    __stcs(orow + 0, o0);
    __stcs(orow + 1, o1);
}

extern "C" void kernel_launch(void* const* d_in, const int* in_sizes, int n_in,
                              void* d_out, int out_size) {
    const float* x = (const float*)d_in[0];
    float* out = (float*)d_out;
    const int threads = 256;
    const int blocks = (NOCT + threads - 1) / threads;  // 12288
    SoftPool2d_850403524762_kernel<<<blocks, threads>>>(x, out);
}

// round 12
// speedup vs baseline: 1.0832x; 1.0832x over previous
#include <cuda_runtime.h>
#include <cuda_bf16.h>

// SoftPool2d: x (16, 96, 256, 256) f32, 2x2 window, stride 2, no pad.
// out (16, 96, 128, 128) f32.
//
// Pure streaming (no reuse): read 402.7MB + write 100.7MB -> HBM-bound.
// R10: same 8-outputs/thread layout as R9, but __launch_bounds__(256, 4)
// raises the ptxas register cap to 64 so all 8 float4 loads stay LIVE in
// registers. R9 failed because ptxas capped regs at 32 and spilled to local
// (L1 39->63%, DRAM 86->76%). MLP_p1=8 only works if the loads are not
// spilled/serialized.

#define H 256
#define W 256
#define HO 128
#define WO 128

// octets of output pixels: (B*C) * HO * (WO/8) = 1536 * 128 * 16
#define NOCT (16 * 96 * 128 * 16)

__device__ __forceinline__ float softpool4(float t0, float t1, float t2, float t3) {
    float m = fmaxf(fmaxf(t0, t1), fmaxf(t2, t3));
    float e0 = __expf(t0 - m);
    float e1 = __expf(t1 - m);
    float e2 = __expf(t2 - m);
    float e3 = __expf(t3 - m);
    float num = fmaf(t0, e0, fmaf(t1, e1, fmaf(t2, e2, t3 * e3)));
    float den = e0 + e1 + e2 + e3;
    return num * __fdividef(1.0f, den);
}

__global__ __launch_bounds__(256, 4) void SoftPool2d_850403524762_kernel(
    const float* __restrict__ x, float* __restrict__ out) {
    int idx = blockIdx.x * blockDim.x + threadIdx.x;
    if (idx >= NOCT) return;

    int wg = idx & 15;          // which 16-col group along W (16 groups)
    int ho = (idx >> 4) & 127;  // output row
    int bc = idx >> 11;         // fused batch*channel plane

    // input rows 2*ho and 2*ho+1 of plane bc; 16 input cols -> 4 float4 per row
    const float4* r0 = (const float4*)(x + (size_t)bc * (H * W) + (size_t)(2 * ho) * W) + 4 * wg;
    const float4* r1 = r0 + (W / 4);

    // 8 independent streaming loads, front-batched, all live in registers
    float4 a0 = __ldcs(r0 + 0);
    float4 a1 = __ldcs(r0 + 1);
    float4 a2 = __ldcs(r0 + 2);
    float4 a3 = __ldcs(r0 + 3);
    float4 b0 = __ldcs(r1 + 0);
    float4 b1 = __ldcs(r1 + 1);
    float4 b2 = __ldcs(r1 + 2);
    float4 b3 = __ldcs(r1 + 3);

    float4 o0, o1;
    o0.x = softpool4(a0.x, a0.y, b0.x, b0.y);
    o0.y = softpool4(a0.z, a0.w, b0.z, b0.w);
    o0.z = softpool4(a1.x, a1.y, b1.x, b1.y);
    o0.w = softpool4(a1.z, a1.w, b1.z, b1.w);
    o1.x = softpool4(a2.x, a2.y, b2.x, b2.y);
    o1.y = softpool4(a2.z, a2.w, b2.z, b2.w);
    o1.z = softpool4(a3.x, a3.y, b3.x, b3.y);
    o1.w = softpool4(a3.z, a3.w, b3.z, b3.w);

    float4* orow = (float4*)(out + (size_t)bc * (HO * WO) + (size_t)ho * WO) + 2 * wg;
    __stcs(orow + 0, o0);
    __stcs(orow + 1, o1);
}

extern "C" void kernel_launch(void* const* d_in, const int* in_sizes, int n_in,
                              void* d_out, int out_size) {
    const float* x = (const float*)d_in[0];
    float* out = (float*)d_out;
    const int threads = 256;
    const int blocks = (NOCT + threads - 1) / threads;  // 12288
    SoftPool2d_850403524762_kernel<<<blocks, threads>>>(x, out);
}